// round 2
// baseline (speedup 1.0000x reference)
#include <cuda_runtime.h>
#include <cstdint>

// Problem constants
#define EDIM   4096
#define BATCH  128
#define NHEAD  32
#define HDIM   128
#define WIN    128
#define TOPK   96

// Scratch (device globals: allocation-free)
__device__ float g_q[BATCH * EDIM];
__device__ float g_k[BATCH * EDIM];
__device__ float g_v[BATCH * EDIM];
__device__ float g_cons[BATCH * EDIM];

// ---------------------------------------------------------------------------
// GEMM: out[M=128, N=4096] = A[128,4096] @ W[4096,4096]^T + bias
// Split-bf16 (hi/lo, 3 products) mma.sync m16n8k16 -> ~fp32-grade precision.
// BM=64 BN=128 BK=32, 256 threads (8 warps: 4m x 2n), cp.async double-buffered.
// ---------------------------------------------------------------------------
#define BM 64
#define BN 128
#define BK 32
#define ASTR 36   // smem row stride (floats): conflict-limited + 16B aligned
#define WSTR 36

__device__ __forceinline__ uint32_t smem_u32(const void* p) {
    return (uint32_t)__cvta_generic_to_shared(p);
}

__device__ __forceinline__ void cp16(void* smem, const void* gmem) {
    asm volatile("cp.async.cg.shared.global [%0], [%1], 16;\n"
                 :: "r"(smem_u32(smem)), "l"(gmem));
}

// Split a float2 into packed bf16x2 hi and lo terms: f = hi + lo (each bf16).
__device__ __forceinline__ void split2(float2 f, uint32_t& hi, uint32_t& lo) {
    uint32_t h;
    asm("cvt.rn.bf16x2.f32 %0, %1, %2;" : "=r"(h) : "f"(f.y), "f"(f.x));
    float h0 = __uint_as_float(h << 16);
    float h1 = __uint_as_float(h & 0xffff0000u);
    float r0 = f.x - h0;
    float r1 = f.y - h1;
    uint32_t l;
    asm("cvt.rn.bf16x2.f32 %0, %1, %2;" : "=r"(l) : "f"(r1), "f"(r0));
    hi = h; lo = l;
}

__device__ __forceinline__ void mma_bf16(float c[4], const uint32_t a[4],
                                         uint32_t b0, uint32_t b1) {
    asm volatile(
        "mma.sync.aligned.m16n8k16.row.col.f32.bf16.bf16.f32 "
        "{%0,%1,%2,%3}, {%4,%5,%6,%7}, {%8,%9}, {%0,%1,%2,%3};\n"
        : "+f"(c[0]), "+f"(c[1]), "+f"(c[2]), "+f"(c[3])
        : "r"(a[0]), "r"(a[1]), "r"(a[2]), "r"(a[3]), "r"(b0), "r"(b1));
}

__device__ __forceinline__ void gemm128(const float* __restrict__ A,
                                        const float* __restrict__ Wt,
                                        const float* __restrict__ bias,
                                        float* __restrict__ out,
                                        float* sm) {
    float* As = sm;                       // [2][BM][ASTR]
    float* Ws = sm + 2 * BM * ASTR;       // [2][BN][WSTR]

    const int tid  = threadIdx.x;
    const int lane = tid & 31;
    const int warp = tid >> 5;
    const int wm   = warp & 3;            // m16 offset within BM
    const int wn   = warp >> 2;           // n64 offset within BN
    const int m0   = blockIdx.y * BM;
    const int n0   = blockIdx.x * BN;

    const int ar = tid >> 3;              // 0..31
    const int ac = (tid & 7) * 4;         // k float4 offset

    float c[8][4];
#pragma unroll
    for (int i = 0; i < 8; i++)
#pragma unroll
        for (int j = 0; j < 4; j++) c[i][j] = 0.f;

    auto prefetch = [&](int stage, int kt) {
        float* Asb = As + stage * BM * ASTR;
        float* Wsb = Ws + stage * BN * WSTR;
        const float* Ag = A + (size_t)(m0 + ar) * EDIM + kt + ac;
        cp16(&Asb[ar * ASTR + ac], Ag);
        cp16(&Asb[(ar + 32) * ASTR + ac], Ag + 32 * (size_t)EDIM);
        const float* Wg = Wt + (size_t)(n0 + ar) * EDIM + kt + ac;
#pragma unroll
        for (int j = 0; j < 4; j++)
            cp16(&Wsb[(ar + 32 * j) * WSTR + ac], Wg + 32 * j * (size_t)EDIM);
        asm volatile("cp.async.commit_group;\n" ::);
    };

    prefetch(0, 0);
    const int T = EDIM / BK;  // 128

    const int mrow = wm * 16 + (lane >> 2);
    const int t2   = (lane & 3) * 2;

    for (int t = 0; t < T; t++) {
        if (t + 1 < T) {
            prefetch((t + 1) & 1, (t + 1) * BK);
            asm volatile("cp.async.wait_group 1;\n" ::);
        } else {
            asm volatile("cp.async.wait_group 0;\n" ::);
        }
        __syncthreads();

        float* Asb = As + (t & 1) * BM * ASTR;
        float* Wsb = Ws + (t & 1) * BN * WSTR;

#pragma unroll
        for (int ch = 0; ch < 2; ch++) {
            const int kk = ch * 16;
            // A fragments (m16 x k16): 4 float2 loads, split hi/lo
            float2 fa0 = *(const float2*)&Asb[mrow * ASTR + kk + t2];
            float2 fa1 = *(const float2*)&Asb[(mrow + 8) * ASTR + kk + t2];
            float2 fa2 = *(const float2*)&Asb[mrow * ASTR + kk + t2 + 8];
            float2 fa3 = *(const float2*)&Asb[(mrow + 8) * ASTR + kk + t2 + 8];
            uint32_t ah[4], al[4];
            split2(fa0, ah[0], al[0]);
            split2(fa1, ah[1], al[1]);
            split2(fa2, ah[2], al[2]);
            split2(fa3, ah[3], al[3]);
#pragma unroll
            for (int nt = 0; nt < 8; nt++) {
                const int nr = wn * 64 + nt * 8 + (lane >> 2);
                float2 fb0 = *(const float2*)&Wsb[nr * WSTR + kk + t2];
                float2 fb1 = *(const float2*)&Wsb[nr * WSTR + kk + t2 + 8];
                uint32_t bh0, bl0, bh1, bl1;
                split2(fb0, bh0, bl0);
                split2(fb1, bh1, bl1);
                mma_bf16(c[nt], ah, bh0, bh1);   // hi*hi
                mma_bf16(c[nt], ah, bl0, bl1);   // hi*lo
                mma_bf16(c[nt], al, bh0, bh1);   // lo*hi
            }
        }
        __syncthreads();
    }

    // Epilogue (C layout of m16n8: row lane>>2, cols 2*(lane&3))
    const int orow  = m0 + wm * 16 + (lane >> 2);
    const int nbase = n0 + wn * 64 + 2 * (lane & 3);
#pragma unroll
    for (int nt = 0; nt < 8; nt++) {
        const int n = nbase + nt * 8;
        const float bv0 = bias[n], bv1 = bias[n + 1];
        out[(size_t)orow * EDIM + n]           = c[nt][0] + bv0;
        out[(size_t)orow * EDIM + n + 1]       = c[nt][1] + bv1;
        out[(size_t)(orow + 8) * EDIM + n]     = c[nt][2] + bv0;
        out[(size_t)(orow + 8) * EDIM + n + 1] = c[nt][3] + bv1;
    }
}

__global__ void __launch_bounds__(256) qkv_gemm(const float* __restrict__ x,
                                                const float* __restrict__ Wq,
                                                const float* __restrict__ bq,
                                                const float* __restrict__ Wk,
                                                const float* __restrict__ bk,
                                                const float* __restrict__ Wv,
                                                const float* __restrict__ bv) {
    extern __shared__ float sm[];
    const float* W; const float* b; float* out;
    if (blockIdx.z == 0)      { W = Wq; b = bq; out = g_q; }
    else if (blockIdx.z == 1) { W = Wk; b = bk; out = g_k; }
    else                      { W = Wv; b = bv; out = g_v; }
    gemm128(x, W, b, out, sm);
}

__global__ void __launch_bounds__(256) out_gemm(const float* __restrict__ Wo,
                                                const float* __restrict__ bo,
                                                float* __restrict__ out) {
    extern __shared__ float sm[];
    gemm128(g_cons, Wo, bo, out, sm);
}

// ---------------------------------------------------------------------------
// Fused ring-write + copy-out + RBF attention (top-96 of 128) per (b,h).
// grid = 4096 blocks, 256 threads, 64KB dynamic smem tile (reused K then V).
// Swizzle: float4 group g of row w stored at slot (g ^ (w&31)).
// ---------------------------------------------------------------------------
__global__ void __launch_bounds__(256) attn_kernel(
    const float* __restrict__ K_ring, const float* __restrict__ V_ring,
    const float* __restrict__ log_sigma, const int* __restrict__ curpos,
    float* __restrict__ out_base) {
    extern __shared__ float tile[];   // [128][128] swizzled
    __shared__ float qs[HDIM];
    __shared__ float sc[WIN];
    __shared__ float pv[WIN];
    __shared__ float red[8];

    const int bh  = blockIdx.x;
    const int b   = bh >> 5;          // / NHEAD
    const int h   = bh & 31;
    const int tid = threadIdx.x;
    const int idx = curpos[0] & (WIN - 1);

    const size_t base   = (size_t)bh * (WIN * HDIM);
    const size_t OUT_O  = (size_t)BATCH * EDIM;                  // 524288
    const size_t SEG    = (size_t)BATCH * NHEAD * WIN * HDIM;    // 67108864

    const float4* Ksrc  = (const float4*)(K_ring + base);
    const float4* Vsrc  = (const float4*)(V_ring + base);
    float4* Kout        = (float4*)(out_base + OUT_O + base);
    float4* Vout        = (float4*)(out_base + OUT_O + SEG + base);
    const float4* knew4 = (const float4*)(g_k + (size_t)b * EDIM + h * HDIM);
    const float4* vnew4 = (const float4*)(g_v + (size_t)b * EDIM + h * HDIM);
    float4* tile4       = (float4*)tile;

    if (tid < HDIM) qs[tid] = g_q[(size_t)b * EDIM + h * HDIM + tid];

    // ---- K: copy to output (with new row at idx) + stage swizzled ----
#pragma unroll 4
    for (int i = tid; i < WIN * HDIM / 4; i += 256) {
        const int w = i >> 5, c4 = i & 31;
        float4 val = (w == idx) ? knew4[c4] : Ksrc[i];
        Kout[i] = val;
        tile4[w * 32 + (c4 ^ (w & 31))] = val;
    }
    __syncthreads();

    // ---- distances / scores ----
    float s = -1e30f;
    if (tid < WIN) {
        const int w = tid;
        const float inv = -0.5f * expf(-2.0f * log_sigma[h]);  // -1/(2*sigma^2)
        float acc = 0.f;
#pragma unroll
        for (int c4 = 0; c4 < 32; c4++) {
            float4 kv = tile4[w * 32 + (c4 ^ (w & 31))];
            float d0 = kv.x - qs[4 * c4 + 0];
            float d1 = kv.y - qs[4 * c4 + 1];
            float d2 = kv.z - qs[4 * c4 + 2];
            float d3 = kv.w - qs[4 * c4 + 3];
            acc += d0 * d0 + d1 * d1 + d2 * d2 + d3 * d3;
        }
        s = acc * inv;
        sc[w] = s;
    }
    __syncthreads();

    // ---- rank (top-96 selection) + max ----
    bool sel = false;
    if (tid < WIN) {
        int cnt = 0;
#pragma unroll 8
        for (int j = 0; j < WIN; j++) {
            float o = sc[j];
            cnt += (o > s) || (o == s && j < tid);
        }
        sel = (cnt < TOPK);
        float m = s;
#pragma unroll
        for (int off = 16; off; off >>= 1)
            m = fmaxf(m, __shfl_xor_sync(0xffffffffu, m, off));
        if ((tid & 31) == 0) red[tid >> 5] = m;
    }
    __syncthreads();
    const float m = fmaxf(fmaxf(red[0], red[1]), fmaxf(red[2], red[3]));

    float e = 0.f;
    if (tid < WIN) {
        e = sel ? expf(s - m) : 0.f;
        float z = e;
#pragma unroll
        for (int off = 16; off; off >>= 1)
            z += __shfl_xor_sync(0xffffffffu, z, off);
        if ((tid & 31) == 0) red[4 + (tid >> 5)] = z;
    }
    __syncthreads();
    const float Z = red[4] + red[5] + red[6] + red[7];
    if (tid < WIN) pv[tid] = e / Z;
    __syncthreads();

    // ---- V: copy to output + stage swizzled (overwrites tile) ----
#pragma unroll 4
    for (int i = tid; i < WIN * HDIM / 4; i += 256) {
        const int w = i >> 5, c4 = i & 31;
        float4 val = (w == idx) ? vnew4[c4] : Vsrc[i];
        Vout[i] = val;
        tile4[w * 32 + (c4 ^ (w & 31))] = val;
    }
    __syncthreads();

    // ---- consensus_d = sum_w p_w * V[w][d] ----
    if (tid < HDIM) {
        const int d = tid;
        const int g = d >> 2, r = d & 3;
        float acc = 0.f;
#pragma unroll 4
        for (int w = 0; w < WIN; w++)
            acc += pv[w] * tile[w * HDIM + (((g ^ (w & 31)) << 2) | r)];
        g_cons[(size_t)b * EDIM + h * HDIM + d] = acc;
    }
}

// ---------------------------------------------------------------------------
extern "C" void kernel_launch(void* const* d_in, const int* in_sizes, int n_in,
                              void* d_out, int out_size) {
    const float* x      = (const float*)d_in[0];
    const float* Wq     = (const float*)d_in[1];
    const float* bq     = (const float*)d_in[2];
    const float* Wk     = (const float*)d_in[3];
    const float* bk     = (const float*)d_in[4];
    const float* Wv     = (const float*)d_in[5];
    const float* bv     = (const float*)d_in[6];
    const float* Wo     = (const float*)d_in[7];
    const float* bo     = (const float*)d_in[8];
    const float* ls     = (const float*)d_in[9];
    const float* K_ring = (const float*)d_in[10];
    const float* V_ring = (const float*)d_in[11];
    const int*   cpos   = (const int*)d_in[12];
    float* out = (float*)d_out;

    const int gemm_smem = (2 * BM * ASTR + 2 * BN * WSTR) * 4;  // 55296 B
    const int attn_smem = WIN * HDIM * 4;                       // 65536 B
    cudaFuncSetAttribute(qkv_gemm, cudaFuncAttributeMaxDynamicSharedMemorySize, gemm_smem);
    cudaFuncSetAttribute(out_gemm, cudaFuncAttributeMaxDynamicSharedMemorySize, gemm_smem);
    cudaFuncSetAttribute(attn_kernel, cudaFuncAttributeMaxDynamicSharedMemorySize, attn_smem);

    dim3 gq(EDIM / BN, BATCH / BM, 3);   // (32, 2, 3)
    qkv_gemm<<<gq, 256, gemm_smem>>>(x, Wq, bq, Wk, bk, Wv, bv);

    attn_kernel<<<BATCH * NHEAD, 256, attn_smem>>>(K_ring, V_ring, ls, cpos, out);

    dim3 go(EDIM / BN, BATCH / BM, 1);   // (32, 2)
    out_gemm<<<go, 256, gemm_smem>>>(Wo, bo, out);
}

// round 3
// speedup vs baseline: 1.6287x; 1.6287x over previous
#include <cuda_runtime.h>
#include <cstdint>

#define EDIM   4096
#define BATCH  128
#define NHEAD  32
#define HDIM   128
#define WIN    128
#define TOPK   96

// Scratch (device globals: allocation-free)
__device__ float    g_q[BATCH * EDIM];
__device__ float    g_k[BATCH * EDIM];
__device__ float    g_v[BATCH * EDIM];
__device__ uint32_t g_xh[BATCH * EDIM / 2];   // x split hi (bf16x2)
__device__ uint32_t g_xl[BATCH * EDIM / 2];   // x split lo
__device__ uint32_t g_ch[BATCH * EDIM / 2];   // consensus hi
__device__ uint32_t g_cl[BATCH * EDIM / 2];   // consensus lo

__device__ __forceinline__ uint32_t smem_u32(const void* p) {
    return (uint32_t)__cvta_generic_to_shared(p);
}
__device__ __forceinline__ void cp16(void* smem, const void* gmem) {
    asm volatile("cp.async.cg.shared.global [%0], [%1], 16;\n"
                 :: "r"(smem_u32(smem)), "l"(gmem));
}

// Split a float2 into packed bf16x2 hi and lo terms: f = hi + lo (each bf16).
__device__ __forceinline__ void split2(float2 f, uint32_t& hi, uint32_t& lo) {
    uint32_t h;
    asm("cvt.rn.bf16x2.f32 %0, %1, %2;" : "=r"(h) : "f"(f.y), "f"(f.x));
    float h0 = __uint_as_float(h << 16);
    float h1 = __uint_as_float(h & 0xffff0000u);
    float r0 = f.x - h0;
    float r1 = f.y - h1;
    uint32_t l;
    asm("cvt.rn.bf16x2.f32 %0, %1, %2;" : "=r"(l) : "f"(r1), "f"(r0));
    hi = h; lo = l;
}

__device__ __forceinline__ void mma_bf16(float c[4], const uint32_t a[4],
                                         uint32_t b0, uint32_t b1) {
    asm volatile(
        "mma.sync.aligned.m16n8k16.row.col.f32.bf16.bf16.f32 "
        "{%0,%1,%2,%3}, {%4,%5,%6,%7}, {%8,%9}, {%0,%1,%2,%3};\n"
        : "+f"(c[0]), "+f"(c[1]), "+f"(c[2]), "+f"(c[3])
        : "r"(a[0]), "r"(a[1]), "r"(a[2]), "r"(a[3]), "r"(b0), "r"(b1));
}

// ---------------------------------------------------------------------------
// Small helper kernels
// ---------------------------------------------------------------------------
__global__ void convert_x(const float* __restrict__ x) {
    int i = blockIdx.x * 256 + threadIdx.x;          // < 262144
    float2 f = ((const float2*)x)[i];
    uint32_t h, l; split2(f, h, l);
    g_xh[i] = h; g_xl[i] = l;
}

__global__ void init_qkv(const float* __restrict__ bq,
                         const float* __restrict__ bk,
                         const float* __restrict__ bv) {
    int i = blockIdx.x * 256 + threadIdx.x;          // < 524288
    int n = i & (EDIM - 1);
    g_q[i] = bq[n]; g_k[i] = bk[n]; g_v[i] = bv[n];
}

__global__ void init_out(const float* __restrict__ bo, float* __restrict__ out) {
    int i = blockIdx.x * 256 + threadIdx.x;          // < 524288
    out[i] = bo[i & (EDIM - 1)];
}

// ---------------------------------------------------------------------------
// GEMM: out[128, N-tile 64] += A[128, Kslab] @ W[Ntile, Kslab]^T
// A pre-split bf16 hi/lo (cp.async); W fp32 LDG -> split once -> bf16 smem.
// BM=128, BN=64, BK=64 per stage, split-K=2 (blockIdx.y), atomicAdd epilogue.
// smem (u32 words/stage=12288): Ah[128][32] +0, Al +4096, Wh[64][32] +8192, Wl +10240
// XOR swizzle: 16B chunk g of row r stored at chunk (g ^ (r&7)).
// ---------------------------------------------------------------------------
#define GK 2048   // K per split
#define GT 32     // stages per split (GK/64)

__device__ __forceinline__ void gemm_body(const uint32_t* __restrict__ Ah_g,
                                          const uint32_t* __restrict__ Al_g,
                                          const float* __restrict__ Wt,
                                          float* __restrict__ out,
                                          uint32_t* sm) {
    const int tid  = threadIdx.x;
    const int lane = tid & 31;
    const int warp = tid >> 5;
    const int n0   = blockIdx.x * 64;
    const int k0   = blockIdx.y * GK;
    const int k0w  = k0 >> 1;
    const int wm   = warp >> 1;      // 0..3 (m32 tiles)
    const int wn   = warp & 1;       // 0..1 (n32 tiles)
    const int rl   = lane >> 2;      // 0..7
    const int kq   = lane & 3;
    const int s4   = rl << 2;

    float c[2][4][4];
#pragma unroll
    for (int i = 0; i < 2; i++)
#pragma unroll
        for (int j = 0; j < 4; j++)
#pragma unroll
            for (int q = 0; q < 4; q++) c[i][j][q] = 0.f;

    const int rA = tid >> 1, gA = (tid & 1) * 4;   // A: 128 rows x 8 chunks
    const int rW = tid >> 2, qW = tid & 3;         // W: 64 rows x 16 float4

    float4 wreg[4];

    auto loadW = [&](int t) {
#pragma unroll
        for (int qi = 0; qi < 4; qi++) {
            int q = qW + qi * 4;
            wreg[qi] = *(const float4*)(Wt + (size_t)(n0 + rW) * EDIM + k0 + t * 64 + 4 * q);
        }
    };
    auto loadA = [&](int t, int buf) {
        uint32_t* dsth = sm + buf * 12288;
        uint32_t* dstl = dsth + 4096;
#pragma unroll
        for (int gi = 0; gi < 4; gi++) {
            int g  = gA + gi;
            int dw = rA * 32 + 4 * (g ^ (rA & 7));
            const uint32_t* srch = Ah_g + (size_t)rA * 2048 + k0w + t * 32 + 4 * g;
            const uint32_t* srcl = Al_g + (size_t)rA * 2048 + k0w + t * 32 + 4 * g;
            cp16(dsth + dw, srch);
            cp16(dstl + dw, srcl);
        }
        asm volatile("cp.async.commit_group;\n" ::);
    };
    auto stW = [&](int buf) {
        uint32_t* dh = sm + buf * 12288 + 8192;
        uint32_t* dl = dh + 2048;
#pragma unroll
        for (int qi = 0; qi < 4; qi++) {
            int q = qW + qi * 4;
            uint32_t h01, l01, h23, l23;
            split2(make_float2(wreg[qi].x, wreg[qi].y), h01, l01);
            split2(make_float2(wreg[qi].z, wreg[qi].w), h23, l23);
            int cc = (2 * q) ^ ((rW & 7) << 2);
            *(uint2*)(dh + rW * 32 + cc) = make_uint2(h01, h23);
            *(uint2*)(dl + rW * 32 + cc) = make_uint2(l01, l23);
        }
    };
    auto compute = [&](int buf) {
        const uint32_t* Ah = sm + buf * 12288;
        const uint32_t* Al = Ah + 4096;
        const uint32_t* Wh = Ah + 8192;
        const uint32_t* Wl = Ah + 10240;
#pragma unroll
        for (int ch = 0; ch < 4; ch++) {
            const int colA = ((ch * 8) ^ s4) + kq;
            const int colB = ((ch * 8 + 4) ^ s4) + kq;
            uint32_t ah[2][4], al[2][4];
#pragma unroll
            for (int mt = 0; mt < 2; mt++) {
                const int R = wm * 32 + mt * 16 + rl;
                ah[mt][0] = Ah[R * 32 + colA];
                ah[mt][1] = Ah[(R + 8) * 32 + colA];
                ah[mt][2] = Ah[R * 32 + colB];
                ah[mt][3] = Ah[(R + 8) * 32 + colB];
                al[mt][0] = Al[R * 32 + colA];
                al[mt][1] = Al[(R + 8) * 32 + colA];
                al[mt][2] = Al[R * 32 + colB];
                al[mt][3] = Al[(R + 8) * 32 + colB];
            }
#pragma unroll
            for (int nt = 0; nt < 4; nt++) {
                const int n = wn * 32 + nt * 8 + rl;
                uint32_t bh0 = Wh[n * 32 + colA], bh1 = Wh[n * 32 + colB];
                uint32_t bl0 = Wl[n * 32 + colA], bl1 = Wl[n * 32 + colB];
#pragma unroll
                for (int mt = 0; mt < 2; mt++) {
                    mma_bf16(c[mt][nt], ah[mt], bh0, bh1);
                    mma_bf16(c[mt][nt], ah[mt], bl0, bl1);
                    mma_bf16(c[mt][nt], al[mt], bh0, bh1);
                }
            }
        }
    };

    loadW(0);
    loadA(0, 0);
    stW(0);
    asm volatile("cp.async.wait_group 0;\n" ::);
    __syncthreads();

    for (int t = 0; t < GT; t++) {
        const int nb = (t + 1) & 1;
        if (t + 1 < GT) { loadW(t + 1); loadA(t + 1, nb); }
        compute(t & 1);
        if (t + 1 < GT) {
            stW(nb);
            asm volatile("cp.async.wait_group 0;\n" ::);
        }
        __syncthreads();
    }

    // Epilogue: atomic accumulate (bias pre-filled by init kernels)
#pragma unroll
    for (int mt = 0; mt < 2; mt++) {
        const int row = wm * 32 + mt * 16 + rl;
#pragma unroll
        for (int nt = 0; nt < 4; nt++) {
            const int n = n0 + wn * 32 + nt * 8 + 2 * kq;
            atomicAdd(&out[(size_t)row * EDIM + n],           c[mt][nt][0]);
            atomicAdd(&out[(size_t)row * EDIM + n + 1],       c[mt][nt][1]);
            atomicAdd(&out[(size_t)(row + 8) * EDIM + n],     c[mt][nt][2]);
            atomicAdd(&out[(size_t)(row + 8) * EDIM + n + 1], c[mt][nt][3]);
        }
    }
}

__global__ void __launch_bounds__(256, 2) qkv_gemm(const float* __restrict__ Wq,
                                                   const float* __restrict__ Wk,
                                                   const float* __restrict__ Wv) {
    extern __shared__ uint32_t sm[];
    const float* W; float* out;
    if (blockIdx.z == 0)      { W = Wq; out = g_q; }
    else if (blockIdx.z == 1) { W = Wk; out = g_k; }
    else                      { W = Wv; out = g_v; }
    gemm_body(g_xh, g_xl, W, out, sm);
}

__global__ void __launch_bounds__(256, 2) out_gemm(const float* __restrict__ Wo,
                                                   float* __restrict__ out) {
    extern __shared__ uint32_t sm[];
    gemm_body(g_ch, g_cl, Wo, out, sm);
}

// ---------------------------------------------------------------------------
// Fused ring-write + copy-out + RBF attention, streaming (no K/V smem tiles).
// 512 threads; each warp iteration owns one whole window row w.
// ---------------------------------------------------------------------------
__global__ void __launch_bounds__(512) attn_kernel(
    const float* __restrict__ K_ring, const float* __restrict__ V_ring,
    const float* __restrict__ log_sigma, const int* __restrict__ curpos,
    float* __restrict__ out_base) {
    __shared__ float  qs[HDIM];
    __shared__ float  sc[WIN];
    __shared__ float  pv[WIN];
    __shared__ float  red[8];
    __shared__ float4 part4[16 * 32];

    const int bh   = blockIdx.x;
    const int b    = bh >> 5;
    const int h    = bh & 31;
    const int tid  = threadIdx.x;
    const int lane = tid & 31;
    const int wp   = tid >> 5;
    const int idx  = curpos[0] & (WIN - 1);

    const size_t base  = (size_t)bh * (WIN * HDIM);
    const size_t OUT_O = (size_t)BATCH * EDIM;
    const size_t SEG   = (size_t)BATCH * NHEAD * WIN * HDIM;

    const float4* Ksrc  = (const float4*)(K_ring + base);
    const float4* Vsrc  = (const float4*)(V_ring + base);
    float4* Kout        = (float4*)(out_base + OUT_O + base);
    float4* Vout        = (float4*)(out_base + OUT_O + SEG + base);
    const float4* knew4 = (const float4*)(g_k + (size_t)b * EDIM + h * HDIM);
    const float4* vnew4 = (const float4*)(g_v + (size_t)b * EDIM + h * HDIM);

    if (tid < HDIM) qs[tid] = g_q[(size_t)b * EDIM + h * HDIM + tid];
    __syncthreads();

    const float inv = -0.5f * expf(-2.0f * log_sigma[h]);

    // ---- K pass: copy + inline squared distance (warp owns row w) ----
#pragma unroll
    for (int j = 0; j < 8; j++) {
        const int i = tid + j * 512;
        const int w = i >> 5;                       // lanes of a warp share w
        float4 val = (w == idx) ? knew4[lane] : Ksrc[i];
        Kout[i] = val;
        float d0 = val.x - qs[lane * 4 + 0];
        float d1 = val.y - qs[lane * 4 + 1];
        float d2 = val.z - qs[lane * 4 + 2];
        float d3 = val.w - qs[lane * 4 + 3];
        float ss = d0 * d0 + d1 * d1 + d2 * d2 + d3 * d3;
#pragma unroll
        for (int o = 16; o; o >>= 1) ss += __shfl_xor_sync(0xffffffffu, ss, o);
        if (lane == 0) sc[w] = ss * inv;
    }
    __syncthreads();

    // ---- top-96 selection + softmax ----
    float s = 0.f, e = 0.f;
    bool sel = false;
    if (tid < WIN) {
        s = sc[tid];
        int cnt = 0;
#pragma unroll 8
        for (int j = 0; j < WIN; j++) {
            float o2 = sc[j];
            cnt += (o2 > s) || (o2 == s && j < tid);
        }
        sel = (cnt < TOPK);
        float mm = s;
#pragma unroll
        for (int o = 16; o; o >>= 1)
            mm = fmaxf(mm, __shfl_xor_sync(0xffffffffu, mm, o));
        if (lane == 0) red[wp] = mm;
    }
    __syncthreads();
    const float m = fmaxf(fmaxf(red[0], red[1]), fmaxf(red[2], red[3]));
    if (tid < WIN) {
        e = sel ? expf(s - m) : 0.f;
        float z = e;
#pragma unroll
        for (int o = 16; o; o >>= 1) z += __shfl_xor_sync(0xffffffffu, z, o);
        if (lane == 0) red[4 + wp] = z;
    }
    __syncthreads();
    if (tid < WIN) pv[tid] = e / (red[4] + red[5] + red[6] + red[7]);
    __syncthreads();

    // ---- V pass: copy + inline weighted accumulation ----
    float4 acc = make_float4(0.f, 0.f, 0.f, 0.f);
#pragma unroll
    for (int j = 0; j < 8; j++) {
        const int i = tid + j * 512;
        const int w = i >> 5;
        float4 val = (w == idx) ? vnew4[lane] : Vsrc[i];
        Vout[i] = val;
        const float p = pv[w];
        acc.x += p * val.x; acc.y += p * val.y;
        acc.z += p * val.z; acc.w += p * val.w;
    }
    part4[wp * 32 + lane] = acc;
    __syncthreads();

    // ---- cross-warp reduce + write consensus as bf16 hi/lo ----
    if (tid < HDIM) {
        const float* pf = (const float*)part4;
        float a = 0.f;
#pragma unroll
        for (int w2 = 0; w2 < 16; w2++) a += pf[w2 * 128 + tid];
        float o = __shfl_xor_sync(0xffffffffu, a, 1);
        if ((tid & 1) == 0) {
            uint32_t hh, ll;
            split2(make_float2(a, o), hh, ll);
            const int wi = bh * 64 + (tid >> 1);
            g_ch[wi] = hh; g_cl[wi] = ll;
        }
    }
}

// ---------------------------------------------------------------------------
extern "C" void kernel_launch(void* const* d_in, const int* in_sizes, int n_in,
                              void* d_out, int out_size) {
    const float* x      = (const float*)d_in[0];
    const float* Wq     = (const float*)d_in[1];
    const float* bq     = (const float*)d_in[2];
    const float* Wk     = (const float*)d_in[3];
    const float* bk     = (const float*)d_in[4];
    const float* Wv     = (const float*)d_in[5];
    const float* bv     = (const float*)d_in[6];
    const float* Wo     = (const float*)d_in[7];
    const float* bo     = (const float*)d_in[8];
    const float* ls     = (const float*)d_in[9];
    const float* K_ring = (const float*)d_in[10];
    const float* V_ring = (const float*)d_in[11];
    const int*   cpos   = (const int*)d_in[12];
    float* out = (float*)d_out;

    const int gemm_smem = 2 * 12288 * 4;   // 98304 B
    cudaFuncSetAttribute(qkv_gemm, cudaFuncAttributeMaxDynamicSharedMemorySize, gemm_smem);
    cudaFuncSetAttribute(out_gemm, cudaFuncAttributeMaxDynamicSharedMemorySize, gemm_smem);

    convert_x<<<1024, 256>>>(x);
    init_qkv<<<2048, 256>>>(bq, bk, bv);
    init_out<<<2048, 256>>>(bo, out);

    qkv_gemm<<<dim3(64, 2, 3), 256, gemm_smem>>>(Wq, Wk, Wv);

    attn_kernel<<<BATCH * NHEAD, 512>>>(K_ring, V_ring, ls, cpos, out);

    out_gemm<<<dim3(64, 2, 1), 256, gemm_smem>>>(Wo, out);
}

// round 7
// speedup vs baseline: 1.7468x; 1.0725x over previous
#include <cuda_runtime.h>
#include <cstdint>

#define EDIM   4096
#define BATCH  128
#define NHEAD  32
#define HDIM   128
#define WIN    128
#define TOPK   96

// Scratch (device globals: allocation-free)
__device__ float    g_q[BATCH * EDIM];
__device__ float    g_k[BATCH * EDIM];
__device__ float    g_v[BATCH * EDIM];
__device__ uint32_t g_xh[BATCH * EDIM / 2];   // x split hi (bf16x2)
__device__ uint32_t g_xl[BATCH * EDIM / 2];   // x split lo
__device__ uint32_t g_ch[BATCH * EDIM / 2];   // consensus hi
__device__ uint32_t g_cl[BATCH * EDIM / 2];   // consensus lo

__device__ __forceinline__ uint32_t smem_u32(const void* p) {
    return (uint32_t)__cvta_generic_to_shared(p);
}
__device__ __forceinline__ void cp16(void* smem, const void* gmem) {
    asm volatile("cp.async.cg.shared.global [%0], [%1], 16;\n"
                 :: "r"(smem_u32(smem)), "l"(gmem));
}

// Split a float2 into packed bf16x2 hi and lo terms: f = hi + lo (each bf16).
__device__ __forceinline__ void split2(float2 f, uint32_t& hi, uint32_t& lo) {
    uint32_t h;
    asm("cvt.rn.bf16x2.f32 %0, %1, %2;" : "=r"(h) : "f"(f.y), "f"(f.x));
    float h0 = __uint_as_float(h << 16);
    float h1 = __uint_as_float(h & 0xffff0000u);
    float r0 = f.x - h0;
    float r1 = f.y - h1;
    uint32_t l;
    asm("cvt.rn.bf16x2.f32 %0, %1, %2;" : "=r"(l) : "f"(r1), "f"(r0));
    hi = h; lo = l;
}

__device__ __forceinline__ void mma_bf16(float c[4], const uint32_t a[4],
                                         uint32_t b0, uint32_t b1) {
    asm volatile(
        "mma.sync.aligned.m16n8k16.row.col.f32.bf16.bf16.f32 "
        "{%0,%1,%2,%3}, {%4,%5,%6,%7}, {%8,%9}, {%0,%1,%2,%3};\n"
        : "+f"(c[0]), "+f"(c[1]), "+f"(c[2]), "+f"(c[3])
        : "r"(a[0]), "r"(a[1]), "r"(a[2]), "r"(a[3]), "r"(b0), "r"(b1));
}

__device__ __forceinline__ void ldsm4(uint32_t* d, uint32_t addr) {
    asm volatile("ldmatrix.sync.aligned.m8n8.x4.shared.b16 {%0,%1,%2,%3}, [%4];"
                 : "=r"(d[0]), "=r"(d[1]), "=r"(d[2]), "=r"(d[3]) : "r"(addr));
}

// ---------------------------------------------------------------------------
// Small helper kernels
// ---------------------------------------------------------------------------
__global__ void convert_x(const float* __restrict__ x) {
    int i = blockIdx.x * 256 + threadIdx.x;          // < 262144
    float2 f = ((const float2*)x)[i];
    uint32_t h, l; split2(f, h, l);
    g_xh[i] = h; g_xl[i] = l;
}

__global__ void init_qkv(const float* __restrict__ bq,
                         const float* __restrict__ bk,
                         const float* __restrict__ bv) {
    int i = blockIdx.x * 256 + threadIdx.x;          // < 524288
    int n = i & (EDIM - 1);
    g_q[i] = bq[n]; g_k[i] = bk[n]; g_v[i] = bv[n];
}

__global__ void init_out(const float* __restrict__ bo, float* __restrict__ out) {
    int i = blockIdx.x * 256 + threadIdx.x;          // < 524288
    out[i] = bo[i & (EDIM - 1)];
}

// ---------------------------------------------------------------------------
// GEMM: out[128, N-tile 64] += A[128, GK] @ W[Ntile, GK]^T
// A pre-split bf16 hi/lo (cp.async); W fp32 LDG -> split once -> bf16 smem.
// BM=128, BN=64, BK=64/stage, split-K=4 (blockIdx.y), atomicAdd epilogue.
// Per-buffer bytes (49152): Ah[128][128B] @0, Al @16384, Wh[64][128B] @32768,
// Wl @40960.  16B chunk g of row r stored at chunk (g ^ (r&7)) -> LDSM-clean.
// Fragments loaded with ldmatrix.x4.
// ---------------------------------------------------------------------------
#define GK 1024   // K per split
#define GT 16     // stages per split (GK/64)

__device__ __forceinline__ void gemm_body(const uint32_t* __restrict__ Ah_g,
                                          const uint32_t* __restrict__ Al_g,
                                          const float* __restrict__ Wt,
                                          float* __restrict__ out,
                                          uint32_t* sm) {
    const int tid  = threadIdx.x;
    const int lane = tid & 31;
    const int warp = tid >> 5;
    const int n0   = blockIdx.x * 64;
    const int k0   = blockIdx.y * GK;
    const int k0w  = k0 >> 1;
    const int wm   = warp >> 1;      // 0..3 (m32 tiles)
    const int wn   = warp & 1;       // 0..1 (n32 tiles)
    const int rl   = lane >> 2;      // 0..7
    const int kq   = lane & 3;
    const uint32_t s0 = smem_u32(sm);

    float c[2][4][4];
#pragma unroll
    for (int i = 0; i < 2; i++)
#pragma unroll
        for (int j = 0; j < 4; j++)
#pragma unroll
            for (int q = 0; q < 4; q++) c[i][j][q] = 0.f;

    const int rA = tid >> 1, gA = (tid & 1) * 4;   // A: 128 rows x 8 chunks
    const int rW = tid >> 2, qW = tid & 3;         // W: 64 rows x 16 float4

    float4 wreg[4];

    auto loadW = [&](int t) {
#pragma unroll
        for (int qi = 0; qi < 4; qi++) {
            int q = qW + qi * 4;
            wreg[qi] = *(const float4*)(Wt + (size_t)(n0 + rW) * EDIM + k0 + t * 64 + 4 * q);
        }
    };
    auto loadA = [&](int t, int buf) {
        uint32_t* dsth = sm + buf * 12288;
        uint32_t* dstl = dsth + 4096;
#pragma unroll
        for (int gi = 0; gi < 4; gi++) {
            int g  = gA + gi;
            int dw = rA * 32 + 4 * (g ^ (rA & 7));
            const uint32_t* srch = Ah_g + (size_t)rA * 2048 + k0w + t * 32 + 4 * g;
            const uint32_t* srcl = Al_g + (size_t)rA * 2048 + k0w + t * 32 + 4 * g;
            cp16(dsth + dw, srch);
            cp16(dstl + dw, srcl);
        }
        asm volatile("cp.async.commit_group;\n" ::);
    };
    auto stW = [&](int buf) {
        uint32_t* dh = sm + buf * 12288 + 8192;
        uint32_t* dl = dh + 2048;
#pragma unroll
        for (int qi = 0; qi < 4; qi++) {
            int q = qW + qi * 4;
            uint32_t h01, l01, h23, l23;
            split2(make_float2(wreg[qi].x, wreg[qi].y), h01, l01);
            split2(make_float2(wreg[qi].z, wreg[qi].w), h23, l23);
            int cc = (2 * q) ^ ((rW & 7) << 2);
            *(uint2*)(dh + rW * 32 + cc) = make_uint2(h01, h23);
            *(uint2*)(dl + rW * 32 + cc) = make_uint2(l01, l23);
        }
    };

    // LDSM per-lane row mapping (constant across stages)
    const int rA0 = wm * 32 + (lane & 15);                    // A rows (mt=0)
    const int hbA = lane >> 4;                                // A k-chunk bit
    const int rW0 = wn * 32 + (lane & 7) + ((lane >> 4) << 3); // W rows (pair=0)
    const int kbW = (lane >> 3) & 1;                          // W k-chunk bit
    const int saA = rA0 & 7, swW = rW0 & 7;

    auto compute = [&](int buf) {
        const uint32_t base  = s0 + buf * 49152;
        const uint32_t aBase = base + rA0 * 128;
        const uint32_t wBase = base + 32768 + rW0 * 128;
#pragma unroll
        for (int ch = 0; ch < 4; ch++) {
            const uint32_t offA = 16u * (uint32_t)((2 * ch + hbA) ^ saA);
            const uint32_t offW = 16u * (uint32_t)((2 * ch + kbW) ^ swW);
            uint32_t ah0[4], ah1[4], al0[4], al1[4], bh[8], bl[8];
            ldsm4(ah0, aBase + offA);
            ldsm4(ah1, aBase + 2048 + offA);
            ldsm4(al0, aBase + 16384 + offA);
            ldsm4(al1, aBase + 18432 + offA);
            ldsm4(bh,     wBase + offW);
            ldsm4(bh + 4, wBase + 2048 + offW);
            ldsm4(bl,     wBase + 8192 + offW);
            ldsm4(bl + 4, wBase + 10240 + offW);
#pragma unroll
            for (int nt = 0; nt < 4; nt++) {
                const uint32_t B0h = bh[nt * 2], B1h = bh[nt * 2 + 1];
                const uint32_t B0l = bl[nt * 2], B1l = bl[nt * 2 + 1];
                mma_bf16(c[0][nt], ah0, B0h, B1h);
                mma_bf16(c[0][nt], ah0, B0l, B1l);
                mma_bf16(c[0][nt], al0, B0h, B1h);
                mma_bf16(c[1][nt], ah1, B0h, B1h);
                mma_bf16(c[1][nt], ah1, B0l, B1l);
                mma_bf16(c[1][nt], al1, B0h, B1h);
            }
        }
    };

    loadW(0);
    loadA(0, 0);
    stW(0);
    asm volatile("cp.async.wait_group 0;\n" ::);
    __syncthreads();

    for (int t = 0; t < GT; t++) {
        const int nb = (t + 1) & 1;
        if (t + 1 < GT) { loadW(t + 1); loadA(t + 1, nb); }
        compute(t & 1);
        if (t + 1 < GT) {
            stW(nb);
            asm volatile("cp.async.wait_group 0;\n" ::);
        }
        __syncthreads();
    }

    // Epilogue: atomic accumulate (bias pre-filled by init kernels)
#pragma unroll
    for (int mt = 0; mt < 2; mt++) {
        const int row = wm * 32 + mt * 16 + rl;
#pragma unroll
        for (int nt = 0; nt < 4; nt++) {
            const int n = n0 + wn * 32 + nt * 8 + 2 * kq;
            atomicAdd(&out[(size_t)row * EDIM + n],           c[mt][nt][0]);
            atomicAdd(&out[(size_t)row * EDIM + n + 1],       c[mt][nt][1]);
            atomicAdd(&out[(size_t)(row + 8) * EDIM + n],     c[mt][nt][2]);
            atomicAdd(&out[(size_t)(row + 8) * EDIM + n + 1], c[mt][nt][3]);
        }
    }
}

__global__ void __launch_bounds__(256, 2) qkv_gemm(const float* __restrict__ Wq,
                                                   const float* __restrict__ Wk,
                                                   const float* __restrict__ Wv) {
    extern __shared__ uint32_t sm[];
    const float* W; float* out;
    if (blockIdx.z == 0)      { W = Wq; out = g_q; }
    else if (blockIdx.z == 1) { W = Wk; out = g_k; }
    else                      { W = Wv; out = g_v; }
    gemm_body(g_xh, g_xl, W, out, sm);
}

__global__ void __launch_bounds__(256, 2) out_gemm(const float* __restrict__ Wo,
                                                   float* __restrict__ out) {
    extern __shared__ uint32_t sm[];
    gemm_body(g_ch, g_cl, Wo, out, sm);
}

// ---------------------------------------------------------------------------
// Fused ring-write + copy-out + RBF attention, streaming.
// ---------------------------------------------------------------------------
__global__ void __launch_bounds__(512) attn_kernel(
    const float* __restrict__ K_ring, const float* __restrict__ V_ring,
    const float* __restrict__ log_sigma, const int* __restrict__ curpos,
    float* __restrict__ out_base) {
    __shared__ float  qs[HDIM];
    __shared__ float  sc[WIN];
    __shared__ float  pv[WIN];
    __shared__ float  red[8];
    __shared__ float4 part4[16 * 32];

    const int bh   = blockIdx.x;
    const int b    = bh >> 5;
    const int h    = bh & 31;
    const int tid  = threadIdx.x;
    const int lane = tid & 31;
    const int wp   = tid >> 5;
    const int idx  = curpos[0] & (WIN - 1);

    const size_t base  = (size_t)bh * (WIN * HDIM);
    const size_t OUT_O = (size_t)BATCH * EDIM;
    const size_t SEG   = (size_t)BATCH * NHEAD * WIN * HDIM;

    const float4* Ksrc  = (const float4*)(K_ring + base);
    const float4* Vsrc  = (const float4*)(V_ring + base);
    float4* Kout        = (float4*)(out_base + OUT_O + base);
    float4* Vout        = (float4*)(out_base + OUT_O + SEG + base);
    const float4* knew4 = (const float4*)(g_k + (size_t)b * EDIM + h * HDIM);
    const float4* vnew4 = (const float4*)(g_v + (size_t)b * EDIM + h * HDIM);

    if (tid < HDIM) qs[tid] = g_q[(size_t)b * EDIM + h * HDIM + tid];
    __syncthreads();

    const float inv = -0.5f * expf(-2.0f * log_sigma[h]);

    // ---- K pass: copy + inline squared distance (warp owns row w) ----
#pragma unroll
    for (int j = 0; j < 8; j++) {
        const int i = tid + j * 512;
        const int w = i >> 5;
        float4 val = (w == idx) ? knew4[lane] : Ksrc[i];
        Kout[i] = val;
        float d0 = val.x - qs[lane * 4 + 0];
        float d1 = val.y - qs[lane * 4 + 1];
        float d2 = val.z - qs[lane * 4 + 2];
        float d3 = val.w - qs[lane * 4 + 3];
        float ss = d0 * d0 + d1 * d1 + d2 * d2 + d3 * d3;
#pragma unroll
        for (int o = 16; o; o >>= 1) ss += __shfl_xor_sync(0xffffffffu, ss, o);
        if (lane == 0) sc[w] = ss * inv;
    }
    __syncthreads();

    // ---- top-96 selection + softmax ----
    float s = 0.f, e = 0.f;
    bool sel = false;
    if (tid < WIN) {
        s = sc[tid];
        int cnt = 0;
#pragma unroll 8
        for (int j = 0; j < WIN; j++) {
            float o2 = sc[j];
            cnt += (o2 > s) || (o2 == s && j < tid);
        }
        sel = (cnt < TOPK);
        float mm = s;
#pragma unroll
        for (int o = 16; o; o >>= 1)
            mm = fmaxf(mm, __shfl_xor_sync(0xffffffffu, mm, o));
        if (lane == 0) red[wp] = mm;
    }
    __syncthreads();
    const float m = fmaxf(fmaxf(red[0], red[1]), fmaxf(red[2], red[3]));
    if (tid < WIN) {
        e = sel ? expf(s - m) : 0.f;
        float z = e;
#pragma unroll
        for (int o = 16; o; o >>= 1) z += __shfl_xor_sync(0xffffffffu, z, o);
        if (lane == 0) red[4 + wp] = z;
    }
    __syncthreads();
    if (tid < WIN) pv[tid] = e / (red[4] + red[5] + red[6] + red[7]);
    __syncthreads();

    // ---- V pass: copy + inline weighted accumulation ----
    float4 acc = make_float4(0.f, 0.f, 0.f, 0.f);
#pragma unroll
    for (int j = 0; j < 8; j++) {
        const int i = tid + j * 512;
        const int w = i >> 5;
        float4 val = (w == idx) ? vnew4[lane] : Vsrc[i];
        Vout[i] = val;
        const float p = pv[w];
        acc.x += p * val.x; acc.y += p * val.y;
        acc.z += p * val.z; acc.w += p * val.w;
    }
    part4[wp * 32 + lane] = acc;
    __syncthreads();

    // ---- cross-warp reduce + write consensus as bf16 hi/lo ----
    if (tid < HDIM) {
        const float* pf = (const float*)part4;
        float a = 0.f;
#pragma unroll
        for (int w2 = 0; w2 < 16; w2++) a += pf[w2 * 128 + tid];
        float o = __shfl_xor_sync(0xffffffffu, a, 1);
        if ((tid & 1) == 0) {
            uint32_t hh, ll;
            split2(make_float2(a, o), hh, ll);
            const int wi = bh * 64 + (tid >> 1);
            g_ch[wi] = hh; g_cl[wi] = ll;
        }
    }
}

// ---------------------------------------------------------------------------
extern "C" void kernel_launch(void* const* d_in, const int* in_sizes, int n_in,
                              void* d_out, int out_size) {
    const float* x      = (const float*)d_in[0];
    const float* Wq     = (const float*)d_in[1];
    const float* bq     = (const float*)d_in[2];
    const float* Wk     = (const float*)d_in[3];
    const float* bk     = (const float*)d_in[4];
    const float* Wv     = (const float*)d_in[5];
    const float* bv     = (const float*)d_in[6];
    const float* Wo     = (const float*)d_in[7];
    const float* bo     = (const float*)d_in[8];
    const float* ls     = (const float*)d_in[9];
    const float* K_ring = (const float*)d_in[10];
    const float* V_ring = (const float*)d_in[11];
    const int*   cpos   = (const int*)d_in[12];
    float* out = (float*)d_out;

    const int gemm_smem = 2 * 12288 * 4;   // 98304 B
    cudaFuncSetAttribute(qkv_gemm, cudaFuncAttributeMaxDynamicSharedMemorySize, gemm_smem);
    cudaFuncSetAttribute(out_gemm, cudaFuncAttributeMaxDynamicSharedMemorySize, gemm_smem);

    convert_x<<<1024, 256>>>(x);
    init_qkv<<<2048, 256>>>(bq, bk, bv);
    init_out<<<2048, 256>>>(bo, out);

    qkv_gemm<<<dim3(64, 4, 3), 256, gemm_smem>>>(Wq, Wk, Wv);

    attn_kernel<<<BATCH * NHEAD, 512>>>(K_ring, V_ring, ls, cpos, out);

    out_gemm<<<dim3(64, 4, 1), 256, gemm_smem>>>(Wo, out);
}